// round 2
// baseline (speedup 1.0000x reference)
#include <cuda_runtime.h>
#include <cstdint>

// Problem constants
#define N_TOK   8192
#define S_CH    32
#define D_DIM   32
#define K_CODE  1024
#define IN_DIM  1024

#define ROWS_PER_CTA 64
#define THREADS_MAIN 128
#define NCTA_X (N_TOK / ROWS_PER_CTA)   // 128
#define NPART  (NCTA_X * S_CH)          // 4096

// Device scratch
__device__ float g_wsq[S_CH * K_CODE];
__device__ float g_partial[NPART];
// k-pair interleaved codebook: for pair kp, element d:
//   lo = W[s][2kp][d], hi = W[s][2kp+1][d]; two d per ulonglong2 (16B aligned)
__device__ ulonglong2 g_Wp[S_CH * (K_CODE / 2) * (D_DIM / 2)];   // 4MB

// ---- packed f32x2 helpers -------------------------------------------------
#define FMA2(acc, a, b) \
    asm("fma.rn.f32x2 %0, %1, %2, %0;" : "+l"(acc) : "l"(a), "l"(b))
#define ADD2(d, a, b) \
    asm("add.rn.f32x2 %0, %1, %2;" : "=l"(d) : "l"(a), "l"(b))
#define FMA2_3(d, a, b, c) \
    asm("fma.rn.f32x2 %0, %1, %2, %3;" : "=l"(d) : "l"(a), "l"(b), "l"(c))
#define PACK2(d, lo, hi) \
    asm("mov.b64 %0, {%1, %2};" : "=l"(d) : "f"(lo), "f"(hi))
#define UNPACK2(lo, hi, v) \
    asm("mov.b64 {%0, %1}, %2;" : "=f"(lo), "=f"(hi) : "l"(v))

// ---------------------------------------------------------------------------
// Kernel 1: wsq[s][k] = sum_d W[s][k][d]^2
// ---------------------------------------------------------------------------
__global__ void wsq_kernel(const float* __restrict__ W) {
    int i = blockIdx.x * blockDim.x + threadIdx.x;
    if (i >= S_CH * K_CODE) return;
    const float4* w4 = reinterpret_cast<const float4*>(W + (size_t)i * D_DIM);
    float s = 0.f;
#pragma unroll
    for (int j = 0; j < 8; j++) {
        float4 v = __ldg(&w4[j]);
        s += v.x * v.x + v.y * v.y + v.z * v.z + v.w * v.w;
    }
    g_wsq[i] = s;
}

// ---------------------------------------------------------------------------
// Kernel 1b: repack W into k-pair-interleaved layout
// ---------------------------------------------------------------------------
__global__ void repack_kernel(const float* __restrict__ W) {
    int i = blockIdx.x * blockDim.x + threadIdx.x;     // 0 .. 262143
    if (i >= S_CH * (K_CODE / 2) * (D_DIM / 2)) return;
    int dpair = i & 15;                 // d/2
    int kp    = (i >> 4) & (K_CODE / 2 - 1);
    int s     = i >> (4 + 9);
    int d = dpair * 2;
    size_t base = ((size_t)s * K_CODE + 2 * kp) * D_DIM + d;
    float a0 = __ldg(&W[base]);          // k0, d
    float a1 = __ldg(&W[base + 1]);      // k0, d+1
    float b0 = __ldg(&W[base + D_DIM]);      // k1, d
    float b1 = __ldg(&W[base + D_DIM + 1]);  // k1, d+1
    ulonglong2 v;
    v.x = ((unsigned long long)__float_as_uint(b0) << 32) | __float_as_uint(a0);
    v.y = ((unsigned long long)__float_as_uint(b1) << 32) | __float_as_uint(a1);
    g_Wp[i] = v;
}

// ---------------------------------------------------------------------------
// Kernel 2: main VQ kernel with packed f32x2 math.
// CTA = (64 n-rows, chunk s). 4 warps own 256-wide k-splits (128 k-pairs).
// Each lane owns 2 rows; per k-pair: lane0 of f32x2 = k0, lane1 = k1.
// ---------------------------------------------------------------------------
__global__ __launch_bounds__(THREADS_MAIN)
void vq_kernel(const float* __restrict__ z,
               const float* __restrict__ W,
               float* __restrict__ out)
{
    __shared__ float s_zT[D_DIM][ROWS_PER_CTA];       // 8KB
    __shared__ __align__(8) float s_wsq[K_CODE];      // 4KB
    __shared__ float s_best[4][ROWS_PER_CTA];
    __shared__ int   s_bidx[4][ROWS_PER_CTA];
    __shared__ float s_loss[ROWS_PER_CTA];

    const int s  = blockIdx.y;
    const int n0 = blockIdx.x * ROWS_PER_CTA;
    const int tid = threadIdx.x;

    // ---- load z tile transposed + wsq row ----
    {
        const float4* zg = reinterpret_cast<const float4*>(z);
        for (int i = tid; i < ROWS_PER_CTA * 8; i += THREADS_MAIN) {
            int r = i >> 3, c = i & 7;
            float4 v = zg[(size_t)(n0 + r) * (IN_DIM / 4) + s * 8 + c];
            s_zT[c * 4 + 0][r] = v.x;
            s_zT[c * 4 + 1][r] = v.y;
            s_zT[c * 4 + 2][r] = v.z;
            s_zT[c * 4 + 3][r] = v.w;
        }
        for (int i = tid; i < K_CODE; i += THREADS_MAIN)
            s_wsq[i] = g_wsq[s * K_CODE + i];
    }
    __syncthreads();

    const int warp = tid >> 5;
    const int lane = tid & 31;
    const int r0 = lane * 2;

    // duplicated-packed z rows: zp[d] = {z_d, z_d}
    unsigned long long zp0[D_DIM], zp1[D_DIM];
    float zsq0 = 0.f, zsq1 = 0.f;
#pragma unroll
    for (int d = 0; d < D_DIM; d++) {
        float2 v = *reinterpret_cast<const float2*>(&s_zT[d][r0]);
        PACK2(zp0[d], v.x, v.x);
        PACK2(zp1[d], v.y, v.y);
        zsq0 = fmaf(v.x, v.x, zsq0);
        zsq1 = fmaf(v.y, v.y, zsq1);
    }
    unsigned long long zsqd0, zsqd1;
    PACK2(zsqd0, zsq0, zsq0);
    PACK2(zsqd1, zsq1, zsq1);
    const unsigned long long NEG2 = 0xC0000000C0000000ULL;  // {-2.f, -2.f}

    float best0 = 3.4e38f, best1 = 3.4e38f;
    int   bi0 = 0, bi1 = 0;

    const int kbase = warp * (K_CODE / 4);                 // 256-wide split
    const ulonglong2* Wp = g_Wp +
        ((size_t)s * (K_CODE / 2) + (kbase >> 1)) * (D_DIM / 2);

#pragma unroll 1
    for (int kk = 0; kk < K_CODE / 8; kk++) {              // 128 k-pairs
        const int k0 = kbase + 2 * kk;

        // 16 x LDG.128 = one k-pair's 2 codewords, interleaved
        ulonglong2 wv[16];
#pragma unroll
        for (int j = 0; j < 16; j++)
            wv[j] = __ldg(&Wp[(size_t)kk * 16 + j]);

        unsigned long long acc0 = 0ULL, acc1 = 0ULL;       // {0.f, 0.f}
#pragma unroll
        for (int j = 0; j < 16; j++) {
            FMA2(acc0, zp0[2 * j + 0], wv[j].x);
            FMA2(acc1, zp1[2 * j + 0], wv[j].x);
            FMA2(acc0, zp0[2 * j + 1], wv[j].y);
            FMA2(acc1, zp1[2 * j + 1], wv[j].y);
        }

        // d2 = (zsq + wsq) - 2*dot  (bit-identical to scalar: 2*dot exact)
        unsigned long long wsqp =
            *reinterpret_cast<const unsigned long long*>(&s_wsq[k0]);
        unsigned long long t0, t1, d2p0, d2p1;
        ADD2(t0, zsqd0, wsqp);
        ADD2(t1, zsqd1, wsqp);
        FMA2_3(d2p0, acc0, NEG2, t0);
        FMA2_3(d2p1, acc1, NEG2, t1);

        float a, b;
        UNPACK2(a, b, d2p0);
        if (a < best0) { best0 = a; bi0 = k0; }
        if (b < best0) { best0 = b; bi0 = k0 + 1; }
        UNPACK2(a, b, d2p1);
        if (a < best1) { best1 = a; bi1 = k0; }
        if (b < best1) { best1 = b; bi1 = k0 + 1; }
    }

    s_best[warp][r0]     = best0;  s_bidx[warp][r0]     = bi0;
    s_best[warp][r0 + 1] = best1;  s_bidx[warp][r0 + 1] = bi1;
    __syncthreads();

    // ---- per-row final reduce (ascending k order), gather, write, loss ----
    if (tid < ROWS_PER_CTA) {
        const int r = tid;
        float b = s_best[0][r];
        int  bi = s_bidx[0][r];
#pragma unroll
        for (int w = 1; w < 4; w++) {
            float cb = s_best[w][r];
            int   ci = s_bidx[w][r];
            if (cb < b) { b = cb; bi = ci; }
        }
        const float4* wrow = reinterpret_cast<const float4*>(
            W + ((size_t)s * K_CODE + bi) * D_DIM);
        float4* orow = reinterpret_cast<float4*>(
            out + (size_t)(n0 + r) * IN_DIM + s * D_DIM);
        float ls = 0.f;
#pragma unroll
        for (int j = 0; j < 8; j++) {
            float4 v = __ldg(&wrow[j]);
            float a0 = v.x - s_zT[j * 4 + 0][r];
            float a1 = v.y - s_zT[j * 4 + 1][r];
            float a2 = v.z - s_zT[j * 4 + 2][r];
            float a3 = v.w - s_zT[j * 4 + 3][r];
            ls = fmaf(a0, a0, ls);
            ls = fmaf(a1, a1, ls);
            ls = fmaf(a2, a2, ls);
            ls = fmaf(a3, a3, ls);
            orow[j] = v;
        }
        s_loss[r] = ls;
    }
    __syncthreads();

    if (tid == 0) {
        float acc = 0.f;
#pragma unroll
        for (int r = 0; r < ROWS_PER_CTA; r++) acc += s_loss[r];
        g_partial[blockIdx.y * gridDim.x + blockIdx.x] = acc;
    }
}

// ---------------------------------------------------------------------------
// Kernel 3: deterministic reduction of partials -> scalar loss
// ---------------------------------------------------------------------------
__global__ void finalize_kernel(float* __restrict__ out, int out_size) {
    __shared__ float sm[256];
    float a = 0.f;
    for (int i = threadIdx.x; i < NPART; i += 256) a += g_partial[i];
    sm[threadIdx.x] = a;
    __syncthreads();
#pragma unroll
    for (int off = 128; off > 0; off >>= 1) {
        if (threadIdx.x < off) sm[threadIdx.x] += sm[threadIdx.x + off];
        __syncthreads();
    }
    if (threadIdx.x == 0) {
        float m = sm[0] / (float)((size_t)N_TOK * S_CH * D_DIM);
        float loss = (float)S_CH * (m + 0.001f * m);
        if (out_size > N_TOK * IN_DIM) out[out_size - 1] = loss;
    }
}

// ---------------------------------------------------------------------------
extern "C" void kernel_launch(void* const* d_in, const int* in_sizes, int n_in,
                              void* d_out, int out_size) {
    const float* z = (const float*)d_in[0];   // (8192, 1024) f32
    const float* W = (const float*)d_in[1];   // (32, 1024, 32) f32
    float* out = (float*)d_out;

    wsq_kernel<<<(S_CH * K_CODE + 127) / 128, 128>>>(W);
    repack_kernel<<<(S_CH * (K_CODE / 2) * (D_DIM / 2) + 127) / 128, 128>>>(W);

    dim3 grid(NCTA_X, S_CH);
    vq_kernel<<<grid, THREADS_MAIN>>>(z, W, out);

    finalize_kernel<<<1, 256>>>(out, out_size);
}

// round 4
// speedup vs baseline: 3.2223x; 3.2223x over previous
#include <cuda_runtime.h>
#include <cuda_fp16.h>
#include <cstdint>

#define N_TOK   8192
#define S_CH    32
#define D_DIM   32
#define K_CODE  1024
#define IN_DIM  1024

#define M_TILE  64
#define THREADS 128
#define MCTA    (N_TOK / M_TILE)       // 128
#define NPART   (MCTA * S_CH)          // 4096

#define NCHUNK     8                   // 1024 k / 128 per chunk
#define CH_ROWS    128
#define ROW_BYTES  80                  // 32 halfs (64B) + 16B pad (ldmatrix bank-safe)
#define HALF_IMG   (CH_ROWS * ROW_BYTES)      // 10240
#define CH_BYTES   (2 * HALF_IMG)             // 20480 (Wh | Wl)

// ---------------- device scratch ----------------
__device__ float g_wsq[S_CH * K_CODE];
__device__ float g_partial[NPART];
__device__ __align__(1024) unsigned char g_Wimg[S_CH * NCHUNK * CH_BYTES]; // 5MB

// ---------------- SMEM layout ----------------
#define SM_MBAR   0
#define SM_Z      64       // 64 x 33 f32 = 8448
#define SM_WSQ    8512     // 4096
#define SM_ZH     12672    // 64 x 80B = 5120
#define SM_ZL     17792    // 5120
#define SM_CAND   22912    // 64 x 16 int = 4096
#define SM_LOSS   27008    // 256
#define SM_B0     28672    // 20480
#define SM_B1     49152    // 20480
#define SMEM_TOTAL 69632

// ---------------- PTX helpers ----------------
__device__ __forceinline__ uint32_t smem_u32(const void* p) {
    uint32_t a;
    asm("{ .reg .u64 t; cvta.to.shared.u64 t, %1; cvt.u32.u64 %0, t; }" : "=r"(a) : "l"(p));
    return a;
}
#define MBAR_INIT(a, c) \
    asm volatile("mbarrier.init.shared.b64 [%0], %1;" :: "r"(a), "r"(c) : "memory")
#define MBAR_EXPECT(a, b) \
    asm volatile("mbarrier.arrive.expect_tx.shared.b64 _, [%0], %1;" :: "r"(a), "r"(b) : "memory")
#define MBAR_WAIT(a, ph) do { \
    uint32_t _m = (a); uint32_t _p = (ph); uint32_t _d; \
    asm volatile("{\n\t.reg .pred p;\n\t" \
        "mbarrier.try_wait.parity.acquire.cta.shared::cta.b64 p, [%1], %2;\n\t" \
        "selp.b32 %0, 1, 0, p;\n\t}" : "=r"(_d) : "r"(_m), "r"(_p) : "memory"); \
    if (!_d) { \
        asm volatile("{\n\t.reg .pred P1;\n\t" \
            "WL_%=:\n\t" \
            "mbarrier.try_wait.parity.acquire.cta.shared::cta.b64 P1, [%0], %1, 0x989680;\n\t" \
            "@P1 bra.uni WD_%=;\n\t" \
            "bra.uni WL_%=;\n\t" \
            "WD_%=:\n\t}" :: "r"(_m), "r"(_p) : "memory"); \
    } } while (0)

__device__ __forceinline__ void bulk_copy(uint32_t dst, const void* src, uint32_t bytes, uint32_t mbar) {
    uint64_t g = (uint64_t)__cvta_generic_to_global(src);
    asm volatile("cp.async.bulk.shared::cta.global.mbarrier::complete_tx::bytes [%0], [%1], %2, [%3];"
        :: "r"(dst), "l"(g), "r"(bytes), "r"(mbar) : "memory");
}
#define LDM_X4(r0, r1, r2, r3, a) \
    asm volatile("ldmatrix.sync.aligned.m8n8.x4.shared.b16 {%0,%1,%2,%3}, [%4];" \
        : "=r"(r0), "=r"(r1), "=r"(r2), "=r"(r3) : "r"(a))
#define MMA16816(c, a, b0, b1) \
    asm volatile("mma.sync.aligned.m16n8k16.row.col.f32.f16.f16.f32 " \
        "{%0,%1,%2,%3}, {%4,%5,%6,%7}, {%8,%9}, {%0,%1,%2,%3};" \
        : "+f"((c)[0]), "+f"((c)[1]), "+f"((c)[2]), "+f"((c)[3]) \
        : "r"((a)[0]), "r"((a)[1]), "r"((a)[2]), "r"((a)[3]), "r"(b0), "r"(b1))

// ---------------------------------------------------------------------------
// Kernel 1: prep — wsq + split W (fp16 hi/lo) into padded streaming image
// ---------------------------------------------------------------------------
__global__ void prep_w(const float* __restrict__ W) {
    int i = blockIdx.x * blockDim.x + threadIdx.x;   // s*1024 + k
    if (i >= S_CH * K_CODE) return;
    int k = i & (K_CODE - 1);
    int s = i >> 10;
    int chunk = k >> 7, row = k & 127;
    size_t base = ((size_t)(s * NCHUNK + chunk)) * CH_BYTES + (size_t)row * ROW_BYTES;
    __half* wh = reinterpret_cast<__half*>(g_Wimg + base);
    __half* wl = reinterpret_cast<__half*>(g_Wimg + base + HALF_IMG);
    const float* wr = W + (size_t)i * D_DIM;
    float sq = 0.f;
#pragma unroll
    for (int d = 0; d < D_DIM; d++) {
        float v = __ldg(&wr[d]);
        sq = fmaf(v, v, sq);
        __half h = __float2half_rn(v);
        __half l = __float2half_rn(v - __half2float(h));
        wh[d] = h;
        wl[d] = l;
    }
    // zero pads (not read by ldmatrix, but keep image deterministic)
#pragma unroll
    for (int d = D_DIM; d < 40; d++) { wh[d] = __float2half_rn(0.f); wl[d] = __float2half_rn(0.f); }
    g_wsq[i] = sq;
}

// ---------------------------------------------------------------------------
// Kernel 2: main — fp16 3-pass mma.sync distances + chained top-2 + recheck
// ---------------------------------------------------------------------------
__global__ __launch_bounds__(THREADS)
void vq_main(const float* __restrict__ z,
             const float* __restrict__ W,
             float* __restrict__ out)
{
    extern __shared__ char smem[];
    const uint32_t sb = smem_u32(smem);
    const int tid  = threadIdx.x;
    const int wid  = tid >> 5;
    const int lane = tid & 31;
    const int s    = blockIdx.y;
    const int n0   = blockIdx.x * M_TILE;

    float* s_z   = reinterpret_cast<float*>(smem + SM_Z);     // stride 33
    float* s_wsq = reinterpret_cast<float*>(smem + SM_WSQ);
    int*   s_cand = reinterpret_cast<int*>(smem + SM_CAND);
    float* s_loss = reinterpret_cast<float*>(smem + SM_LOSS);

    if (tid == 0) { MBAR_INIT(sb + SM_MBAR, 1); MBAR_INIT(sb + SM_MBAR + 8, 1); }
    __syncthreads();

    // kick off B copies for chunks 0, 1
    if (tid == 0) {
        MBAR_EXPECT(sb + SM_MBAR, CH_BYTES);
        bulk_copy(sb + SM_B0, g_Wimg + (size_t)(s * NCHUNK + 0) * CH_BYTES, CH_BYTES, sb + SM_MBAR);
        MBAR_EXPECT(sb + SM_MBAR + 8, CH_BYTES);
        bulk_copy(sb + SM_B1, g_Wimg + (size_t)(s * NCHUNK + 1) * CH_BYTES, CH_BYTES, sb + SM_MBAR + 8);
    }

    // ---- stage z (fp32 + fp16 hi/lo) and wsq ----
    {
        const int r = tid >> 1;                 // 0..63
        const int h = tid & 1;                  // half of the row
        const float4* zr = reinterpret_cast<const float4*>(
            z + (size_t)(n0 + r) * IN_DIM + s * D_DIM) + h * 4;
        __half* zh = reinterpret_cast<__half*>(smem + SM_ZH) + r * 40 + h * 16;
        __half* zl = reinterpret_cast<__half*>(smem + SM_ZL) + r * 40 + h * 16;
        float*  zf = s_z + r * 33 + h * 16;
#pragma unroll
        for (int j = 0; j < 4; j++) {
            float4 v = zr[j];
            float vv[4] = {v.x, v.y, v.z, v.w};
#pragma unroll
            for (int c = 0; c < 4; c++) {
                int d = j * 4 + c;
                zf[d] = vv[c];
                __half hh = __float2half_rn(vv[c]);
                zh[d] = hh;
                zl[d] = __float2half_rn(vv[c] - __half2float(hh));
            }
        }
#pragma unroll
        for (int j = 0; j < K_CODE / THREADS; j++)
            s_wsq[tid + j * THREADS] = g_wsq[s * K_CODE + tid + j * THREADS];
    }
    __syncthreads();

    // ---- A fragments (once): zh/zl, 2 k-steps each ----
    uint32_t Ah[2][4], Al[2][4];
    {
        const int rowoff = wid * 16 + ((lane >> 3) & 1) * 8 + (lane & 7);
        const int kb = (lane >> 4) & 1;
#pragma unroll
        for (int ks = 0; ks < 2; ks++) {
            uint32_t a = sb + SM_ZH + rowoff * ROW_BYTES + ks * 32 + kb * 16;
            LDM_X4(Ah[ks][0], Ah[ks][1], Ah[ks][2], Ah[ks][3], a);
            a = sb + SM_ZL + rowoff * ROW_BYTES + ks * 32 + kb * 16;
            LDM_X4(Al[ks][0], Al[ks][1], Al[ks][2], Al[ks][3], a);
        }
    }

    const int g   = lane >> 2;    // row in m16 group
    const int tig = lane & 3;     // col group

    // 4 chains per thread: (rowA, rowB) x (tile0, tile1), top-2 each
    float b1[4], b2[4];
    int   i1[4], i2[4];
#pragma unroll
    for (int c = 0; c < 4; c++) { b1[c] = 3.4e38f; b2[c] = 3.4e38f; i1[c] = 0; i2[c] = 0; }

    // B ldmatrix lane address pieces
    const int bnrow = ((lane & 16) ? 8 : 0) + (lane & 7);
    const int bkb   = (lane >> 3) & 1;

#pragma unroll 1
    for (int c = 0; c < NCHUNK; c++) {
        MBAR_WAIT(sb + SM_MBAR + (c & 1) * 8, (c >> 1) & 1);
        const uint32_t whb = sb + ((c & 1) ? SM_B1 : SM_B0);
        const uint32_t wlb = whb + HALF_IMG;

#pragma unroll 1
        for (int g2 = 0; g2 < 8; g2++) {
            const uint32_t boff = (uint32_t)(g2 * 16 + bnrow) * ROW_BYTES + bkb * 16;
            uint32_t bh0[4], bh1[4], bl0[4], bl1[4];
            LDM_X4(bh0[0], bh0[1], bh0[2], bh0[3], whb + boff);        // ks0
            LDM_X4(bh1[0], bh1[1], bh1[2], bh1[3], whb + boff + 32);   // ks1
            LDM_X4(bl0[0], bl0[1], bl0[2], bl0[3], wlb + boff);
            LDM_X4(bl1[0], bl1[1], bl1[2], bl1[3], wlb + boff + 32);

            float acc0[4] = {0.f, 0.f, 0.f, 0.f};
            float acc1[4] = {0.f, 0.f, 0.f, 0.f};
            // tile0 (cols n0..n0+7)
            MMA16816(acc0, Ah[0], bh0[0], bh0[1]);
            MMA16816(acc0, Ah[1], bh1[0], bh1[1]);
            MMA16816(acc0, Ah[0], bl0[0], bl0[1]);
            MMA16816(acc0, Ah[1], bl1[0], bl1[1]);
            MMA16816(acc0, Al[0], bh0[0], bh0[1]);
            MMA16816(acc0, Al[1], bh1[0], bh1[1]);
            // tile1 (cols n0+8..n0+15)
            MMA16816(acc1, Ah[0], bh0[2], bh0[3]);
            MMA16816(acc1, Ah[1], bh1[2], bh1[3]);
            MMA16816(acc1, Ah[0], bl0[2], bl0[3]);
            MMA16816(acc1, Ah[1], bl1[2], bl1[3]);
            MMA16816(acc1, Al[0], bh0[2], bh0[3]);
            MMA16816(acc1, Al[1], bh1[2], bh1[3]);

            const int kbase = c * 128 + g2 * 16;
            const int col0 = kbase + tig * 2;
            const int col2 = kbase + 8 + tig * 2;
            float2 w01 = *reinterpret_cast<const float2*>(&s_wsq[col0]);
            float2 w23 = *reinterpret_cast<const float2*>(&s_wsq[col2]);

            // chain 0: rowA/tile0 ; chain 1: rowA/tile1 ;
            // chain 2: rowB/tile0 ; chain 3: rowB/tile1
            float v;
#define UPD(ch, val, idx) do { \
            v = (val); \
            bool lt1 = v < b1[ch]; bool lt2 = v < b2[ch]; \
            float nb2 = lt1 ? b1[ch] : v; int ni2 = lt1 ? i1[ch] : (idx); \
            b2[ch] = lt2 ? nb2 : b2[ch]; i2[ch] = lt2 ? ni2 : i2[ch]; \
            b1[ch] = lt1 ? v : b1[ch];  i1[ch] = lt1 ? (idx) : i1[ch]; } while (0)

            UPD(0, fmaf(-2.f, acc0[0], w01.x), col0);
            UPD(0, fmaf(-2.f, acc0[1], w01.y), col0 + 1);
            UPD(1, fmaf(-2.f, acc1[0], w23.x), col2);
            UPD(1, fmaf(-2.f, acc1[1], w23.y), col2 + 1);
            UPD(2, fmaf(-2.f, acc0[2], w01.x), col0);
            UPD(2, fmaf(-2.f, acc0[3], w01.y), col0 + 1);
            UPD(3, fmaf(-2.f, acc1[2], w23.x), col2);
            UPD(3, fmaf(-2.f, acc1[3], w23.y), col2 + 1);
#undef UPD
        }
        __syncthreads();
        if (tid == 0 && c + 2 < NCHUNK) {
            MBAR_EXPECT(sb + SM_MBAR + (c & 1) * 8, CH_BYTES);
            bulk_copy(sb + ((c & 1) ? SM_B1 : SM_B0),
                      g_Wimg + (size_t)(s * NCHUNK + c + 2) * CH_BYTES, CH_BYTES,
                      sb + SM_MBAR + (c & 1) * 8);
        }
    }

    // ---- write candidates: 16 per row ----
    {
        const int rowA = wid * 16 + g;
        const int rowB = rowA + 8;
        s_cand[rowA * 16 + tig * 4 + 0] = i1[0];
        s_cand[rowA * 16 + tig * 4 + 1] = i2[0];
        s_cand[rowA * 16 + tig * 4 + 2] = i1[1];
        s_cand[rowA * 16 + tig * 4 + 3] = i2[1];
        s_cand[rowB * 16 + tig * 4 + 0] = i1[2];
        s_cand[rowB * 16 + tig * 4 + 1] = i2[2];
        s_cand[rowB * 16 + tig * 4 + 2] = i1[3];
        s_cand[rowB * 16 + tig * 4 + 3] = i2[3];
    }
    __syncthreads();

    // ---- exact fp32 recheck (thread r < 64 owns row r) ----
    if (tid < M_TILE) {
        const int r = tid;
        float zr[D_DIM];
#pragma unroll
        for (int d = 0; d < D_DIM; d++) zr[d] = s_z[r * 33 + d];
        float zsq = 0.f;
#pragma unroll
        for (int d = 0; d < D_DIM; d++) zsq = fmaf(zr[d], zr[d], zsq);

        float bestd = 3.4e38f;
        int   besti = K_CODE;
#pragma unroll 1
        for (int cc = 0; cc < 16; cc++) {
            int k = s_cand[r * 16 + cc];
            const float4* wr = reinterpret_cast<const float4*>(
                W + ((size_t)s * K_CODE + k) * D_DIM);
            float dot = 0.f;
#pragma unroll
            for (int j = 0; j < 8; j++) {
                float4 vv = __ldg(&wr[j]);
                dot = fmaf(zr[j * 4 + 0], vv.x, dot);
                dot = fmaf(zr[j * 4 + 1], vv.y, dot);
                dot = fmaf(zr[j * 4 + 2], vv.z, dot);
                dot = fmaf(zr[j * 4 + 3], vv.w, dot);
            }
            float d2 = (zsq + s_wsq[k]) - 2.0f * dot;
            if (d2 < bestd || (d2 == bestd && k < besti)) { bestd = d2; besti = k; }
        }

        // gather winner, write output row-chunk, loss contribution
        const float4* wr = reinterpret_cast<const float4*>(
            W + ((size_t)s * K_CODE + besti) * D_DIM);
        float4* orow = reinterpret_cast<float4*>(
            out + (size_t)(n0 + r) * IN_DIM + s * D_DIM);
        float ls = 0.f;
#pragma unroll
        for (int j = 0; j < 8; j++) {
            float4 vv = __ldg(&wr[j]);
            float a0 = vv.x - zr[j * 4 + 0];
            float a1 = vv.y - zr[j * 4 + 1];
            float a2 = vv.z - zr[j * 4 + 2];
            float a3 = vv.w - zr[j * 4 + 3];
            ls = fmaf(a0, a0, ls); ls = fmaf(a1, a1, ls);
            ls = fmaf(a2, a2, ls); ls = fmaf(a3, a3, ls);
            orow[j] = vv;
        }
        s_loss[r] = ls;
    }
    __syncthreads();

    if (tid == 0) {
        float acc = 0.f;
#pragma unroll
        for (int q = 0; q < M_TILE; q++) acc += s_loss[q];
        g_partial[s * MCTA + blockIdx.x] = acc;
    }
}

// ---------------------------------------------------------------------------
// Kernel 3: deterministic loss finalize
// ---------------------------------------------------------------------------
__global__ void finalize_kernel(float* __restrict__ out, int out_size) {
    __shared__ float sm[256];
    float a = 0.f;
    for (int i = threadIdx.x; i < NPART; i += 256) a += g_partial[i];
    sm[threadIdx.x] = a;
    __syncthreads();
#pragma unroll
    for (int off = 128; off > 0; off >>= 1) {
        if (threadIdx.x < off) sm[threadIdx.x] += sm[threadIdx.x + off];
        __syncthreads();
    }
    if (threadIdx.x == 0) {
        float m = sm[0] / (float)((size_t)N_TOK * S_CH * D_DIM);
        float loss = (float)S_CH * (m + 0.001f * m);
        if (out_size > N_TOK * IN_DIM) out[out_size - 1] = loss;
    }
}

// ---------------------------------------------------------------------------
extern "C" void kernel_launch(void* const* d_in, const int* in_sizes, int n_in,
                              void* d_out, int out_size) {
    const float* z = (const float*)d_in[0];   // (8192, 1024) f32
    const float* W = (const float*)d_in[1];   // (32, 1024, 32) f32
    float* out = (float*)d_out;

    cudaFuncSetAttribute(vq_main, cudaFuncAttributeMaxDynamicSharedMemorySize, SMEM_TOTAL);

    prep_w<<<(S_CH * K_CODE + 127) / 128, 128>>>(W);

    dim3 grid(MCTA, S_CH);
    vq_main<<<grid, THREADS, SMEM_TOTAL>>>(z, W, out);

    finalize_kernel<<<1, 256>>>(out, out_size);
}

// round 5
// speedup vs baseline: 4.6933x; 1.4565x over previous
#include <cuda_runtime.h>
#include <cuda_fp16.h>
#include <cstdint>

#define N_TOK   8192
#define S_CH    32
#define D_DIM   32
#define K_CODE  1024
#define IN_DIM  1024

#define M_TILE  64
#define THREADS 128
#define MCTA    (N_TOK / M_TILE)       // 128
#define NPART   (MCTA * S_CH)          // 4096

#define NCHUNK     8
#define CH_ROWS    128
#define ROW_BYTES  80                  // 32 halfs + 16B pad (ldmatrix bank-safe)
#define CH_BYTES   (CH_ROWS * ROW_BYTES)      // 10240 (hi image only)

// ---------------- device scratch ----------------
__device__ float g_wsq[S_CH * K_CODE];
__device__ float g_partial[NPART];
__device__ unsigned int g_done = 0;
__device__ __align__(1024) unsigned char g_Wimg[S_CH * NCHUNK * CH_BYTES]; // 2.6MB

// ---------------- SMEM layout ----------------
#define SM_MBAR   0
#define SM_Z      64       // 64 x 33 f32 = 8448
#define SM_WSQ    8512     // 4096
#define SM_ZH     12608    // 64 x 80B = 5120 (half(-2z) image)
#define SM_CANDV  17728    // 64 x 24 f32 = 6144
#define SM_CANDI  23872    // 64 x 24 int = 6144
#define SM_LOSS   30016    // 256
#define SM_B0     30720    // 10240
#define SM_B1     40960    // 10240
#define SMEM_TOTAL 51200

// ---------------- PTX helpers ----------------
__device__ __forceinline__ uint32_t smem_u32(const void* p) {
    uint32_t a;
    asm("{ .reg .u64 t; cvta.to.shared.u64 t, %1; cvt.u32.u64 %0, t; }" : "=r"(a) : "l"(p));
    return a;
}
#define MBAR_INIT(a, c) \
    asm volatile("mbarrier.init.shared.b64 [%0], %1;" :: "r"(a), "r"(c) : "memory")
#define MBAR_EXPECT(a, b) \
    asm volatile("mbarrier.arrive.expect_tx.shared.b64 _, [%0], %1;" :: "r"(a), "r"(b) : "memory")
#define MBAR_WAIT(a, ph) do { \
    uint32_t _m = (a); uint32_t _p = (ph); uint32_t _d; \
    asm volatile("{\n\t.reg .pred p;\n\t" \
        "mbarrier.try_wait.parity.acquire.cta.shared::cta.b64 p, [%1], %2;\n\t" \
        "selp.b32 %0, 1, 0, p;\n\t}" : "=r"(_d) : "r"(_m), "r"(_p) : "memory"); \
    if (!_d) { \
        asm volatile("{\n\t.reg .pred P1;\n\t" \
            "WL_%=:\n\t" \
            "mbarrier.try_wait.parity.acquire.cta.shared::cta.b64 P1, [%0], %1, 0x989680;\n\t" \
            "@P1 bra.uni WD_%=;\n\t" \
            "bra.uni WL_%=;\n\t" \
            "WD_%=:\n\t}" :: "r"(_m), "r"(_p) : "memory"); \
    } } while (0)

__device__ __forceinline__ void bulk_copy(uint32_t dst, const void* src, uint32_t bytes, uint32_t mbar) {
    uint64_t g = (uint64_t)__cvta_generic_to_global(src);
    asm volatile("cp.async.bulk.shared::cta.global.mbarrier::complete_tx::bytes [%0], [%1], %2, [%3];"
        :: "r"(dst), "l"(g), "r"(bytes), "r"(mbar) : "memory");
}
#define LDM_X4(r0, r1, r2, r3, a) \
    asm volatile("ldmatrix.sync.aligned.m8n8.x4.shared.b16 {%0,%1,%2,%3}, [%4];" \
        : "=r"(r0), "=r"(r1), "=r"(r2), "=r"(r3) : "r"(a))
#define MMA16816(c, a, b0, b1) \
    asm volatile("mma.sync.aligned.m16n8k16.row.col.f32.f16.f16.f32 " \
        "{%0,%1,%2,%3}, {%4,%5,%6,%7}, {%8,%9}, {%0,%1,%2,%3};" \
        : "+f"((c)[0]), "+f"((c)[1]), "+f"((c)[2]), "+f"((c)[3]) \
        : "r"((a)[0]), "r"((a)[1]), "r"((a)[2]), "r"((a)[3]), "r"(b0), "r"(b1))
// first MMA of a chain: D = A*B + {c0,c1,c0,c1}  (wsq init, fp32 exact)
#define MMA16816_INIT(c, a, b0, b1, c0v, c1v) \
    asm volatile("mma.sync.aligned.m16n8k16.row.col.f32.f16.f16.f32 " \
        "{%0,%1,%2,%3}, {%4,%5,%6,%7}, {%8,%9}, {%10,%11,%12,%13};" \
        : "=f"((c)[0]), "=f"((c)[1]), "=f"((c)[2]), "=f"((c)[3]) \
        : "r"((a)[0]), "r"((a)[1]), "r"((a)[2]), "r"((a)[3]), "r"(b0), "r"(b1), \
          "f"(c0v), "f"(c1v), "f"(c0v), "f"(c1v))

// ---------------------------------------------------------------------------
// Kernel 1: prep — wsq + fp16-hi W image (padded rows for ldmatrix)
// ---------------------------------------------------------------------------
__global__ void prep_w(const float* __restrict__ W) {
    int i = blockIdx.x * blockDim.x + threadIdx.x;   // s*1024 + k
    if (i >= S_CH * K_CODE) return;
    int k = i & (K_CODE - 1);
    int s = i >> 10;
    int chunk = k >> 7, row = k & 127;
    __half2* wh = reinterpret_cast<__half2*>(
        g_Wimg + (size_t)(s * NCHUNK + chunk) * CH_BYTES + (size_t)row * ROW_BYTES);
    const float4* wr = reinterpret_cast<const float4*>(W + (size_t)i * D_DIM);
    float sq = 0.f;
#pragma unroll
    for (int j = 0; j < 8; j++) {
        float4 v = __ldg(&wr[j]);
        sq = fmaf(v.x, v.x, sq); sq = fmaf(v.y, v.y, sq);
        sq = fmaf(v.z, v.z, sq); sq = fmaf(v.w, v.w, sq);
        wh[j * 2 + 0] = __floats2half2_rn(v.x, v.y);
        wh[j * 2 + 1] = __floats2half2_rn(v.z, v.w);
    }
#pragma unroll
    for (int j = 16; j < 20; j++) wh[j] = __floats2half2_rn(0.f, 0.f);  // pad
    g_wsq[i] = sq;
}

// ---------------------------------------------------------------------------
// Kernel 2: main — 1-pass fp16 screening + top-3 chains + band recheck
// ---------------------------------------------------------------------------
__global__ __launch_bounds__(THREADS)
void vq_main(const float* __restrict__ z,
             const float* __restrict__ W,
             float* __restrict__ out,
             int out_size)
{
    extern __shared__ char smem[];
    const uint32_t sb = smem_u32(smem);
    const int tid  = threadIdx.x;
    const int wid  = tid >> 5;
    const int lane = tid & 31;
    const int s    = blockIdx.y;
    const int n0   = blockIdx.x * M_TILE;

    float* s_z     = reinterpret_cast<float*>(smem + SM_Z);     // stride 33
    float* s_wsq   = reinterpret_cast<float*>(smem + SM_WSQ);
    float* s_candv = reinterpret_cast<float*>(smem + SM_CANDV);
    int*   s_candi = reinterpret_cast<int*>(smem + SM_CANDI);
    float* s_loss  = reinterpret_cast<float*>(smem + SM_LOSS);

    if (tid == 0) { MBAR_INIT(sb + SM_MBAR, 1); MBAR_INIT(sb + SM_MBAR + 8, 1); }
    __syncthreads();

    if (tid == 0) {
        MBAR_EXPECT(sb + SM_MBAR, CH_BYTES);
        bulk_copy(sb + SM_B0, g_Wimg + (size_t)(s * NCHUNK + 0) * CH_BYTES, CH_BYTES, sb + SM_MBAR);
        MBAR_EXPECT(sb + SM_MBAR + 8, CH_BYTES);
        bulk_copy(sb + SM_B1, g_Wimg + (size_t)(s * NCHUNK + 1) * CH_BYTES, CH_BYTES, sb + SM_MBAR + 8);
    }

    // ---- stage z (fp32) + A image half(-2z) + wsq ----
    {
        const int r = tid >> 1;
        const int h = tid & 1;
        const float4* zr = reinterpret_cast<const float4*>(
            z + (size_t)(n0 + r) * IN_DIM + s * D_DIM) + h * 4;
        __half2* zh = reinterpret_cast<__half2*>(smem + SM_ZH + r * ROW_BYTES + h * 32);
        float*   zf = s_z + r * 33 + h * 16;
#pragma unroll
        for (int j = 0; j < 4; j++) {
            float4 v = zr[j];
            zf[j * 4 + 0] = v.x; zf[j * 4 + 1] = v.y;
            zf[j * 4 + 2] = v.z; zf[j * 4 + 3] = v.w;
            zh[j * 2 + 0] = __floats2half2_rn(-2.f * v.x, -2.f * v.y);
            zh[j * 2 + 1] = __floats2half2_rn(-2.f * v.z, -2.f * v.w);
        }
#pragma unroll
        for (int j = 0; j < K_CODE / THREADS; j++)
            s_wsq[tid + j * THREADS] = g_wsq[s * K_CODE + tid + j * THREADS];
    }
    __syncthreads();

    // ---- A fragments (hi only, 2 k-steps) ----
    uint32_t Ah[2][4];
    {
        const int rowoff = wid * 16 + ((lane >> 3) & 1) * 8 + (lane & 7);
        const int kb = (lane >> 4) & 1;
#pragma unroll
        for (int ks = 0; ks < 2; ks++) {
            uint32_t a = sb + SM_ZH + rowoff * ROW_BYTES + ks * 32 + kb * 16;
            LDM_X4(Ah[ks][0], Ah[ks][1], Ah[ks][2], Ah[ks][3], a);
        }
    }

    const int g   = lane >> 2;    // row within m16 block
    const int tig = lane & 3;     // col group

    // 4 chains/thread: (rowA,tile0) (rowA,tile1) (rowB,tile0) (rowB,tile1), top-3
    float b1[4], b2[4], b3[4];
    int   i1[4], i2[4], i3[4];
#pragma unroll
    for (int c = 0; c < 4; c++) {
        b1[c] = 3.4e38f; b2[c] = 3.4e38f; b3[c] = 3.4e38f;
        i1[c] = 0; i2[c] = 0; i3[c] = 0;
    }

#define INS3(ch, val, idx) do { \
    float _v = (val); \
    bool _l1 = _v < b1[ch], _l2 = _v < b2[ch], _l3 = _v < b3[ch]; \
    b3[ch] = _l3 ? (_l2 ? b2[ch] : _v) : b3[ch]; \
    i3[ch] = _l3 ? (_l2 ? i2[ch] : (idx)) : i3[ch]; \
    b2[ch] = _l2 ? (_l1 ? b1[ch] : _v) : b2[ch]; \
    i2[ch] = _l2 ? (_l1 ? i1[ch] : (idx)) : i2[ch]; \
    b1[ch] = _l1 ? _v : b1[ch]; \
    i1[ch] = _l1 ? (idx) : i1[ch]; } while (0)

    const int bnrow = ((lane & 16) ? 8 : 0) + (lane & 7);
    const int bkb   = (lane >> 3) & 1;

#pragma unroll 1
    for (int c = 0; c < NCHUNK; c++) {
        MBAR_WAIT(sb + SM_MBAR + (c & 1) * 8, (c >> 1) & 1);
        const uint32_t whb = sb + ((c & 1) ? SM_B1 : SM_B0);

#pragma unroll 1
        for (int g2 = 0; g2 < 8; g2++) {
            const uint32_t boff = (uint32_t)(g2 * 16 + bnrow) * ROW_BYTES + bkb * 16;
            uint32_t bh0[4], bh1[4];
            LDM_X4(bh0[0], bh0[1], bh0[2], bh0[3], whb + boff);        // ks0
            LDM_X4(bh1[0], bh1[1], bh1[2], bh1[3], whb + boff + 32);   // ks1

            const int kbase = c * 128 + g2 * 16;
            const int col0 = kbase + tig * 2;
            const int col2 = kbase + 8 + tig * 2;
            float2 w01 = *reinterpret_cast<const float2*>(&s_wsq[col0]);
            float2 w23 = *reinterpret_cast<const float2*>(&s_wsq[col2]);

            float acc0[4], acc1[4];
            // acc = wsq - 2*z.w_h (C-initialized with wsq)
            MMA16816_INIT(acc0, Ah[0], bh0[0], bh0[1], w01.x, w01.y);
            MMA16816     (acc0, Ah[1], bh1[0], bh1[1]);
            MMA16816_INIT(acc1, Ah[0], bh0[2], bh0[3], w23.x, w23.y);
            MMA16816     (acc1, Ah[1], bh1[2], bh1[3]);

            INS3(0, acc0[0], col0);
            INS3(0, acc0[1], col0 + 1);
            INS3(1, acc1[0], col2);
            INS3(1, acc1[1], col2 + 1);
            INS3(2, acc0[2], col0);
            INS3(2, acc0[3], col0 + 1);
            INS3(3, acc1[2], col2);
            INS3(3, acc1[3], col2 + 1);
        }
        __syncthreads();
        if (tid == 0 && c + 2 < NCHUNK) {
            MBAR_EXPECT(sb + SM_MBAR + (c & 1) * 8, CH_BYTES);
            bulk_copy(sb + ((c & 1) ? SM_B1 : SM_B0),
                      g_Wimg + (size_t)(s * NCHUNK + c + 2) * CH_BYTES, CH_BYTES,
                      sb + SM_MBAR + (c & 1) * 8);
        }
    }
#undef INS3

    // ---- dump candidates: 24 per row (8 chains x top-3) ----
    {
        const int rowA = wid * 16 + g;
        const int rowB = rowA + 8;
#pragma unroll
        for (int t = 0; t < 2; t++) {
            int baseA = rowA * 24 + t * 12 + tig * 3;
            int baseB = rowB * 24 + t * 12 + tig * 3;
            int chA = t, chB = 2 + t;
            s_candv[baseA + 0] = b1[chA]; s_candi[baseA + 0] = i1[chA];
            s_candv[baseA + 1] = b2[chA]; s_candi[baseA + 1] = i2[chA];
            s_candv[baseA + 2] = b3[chA]; s_candi[baseA + 2] = i3[chA];
            s_candv[baseB + 0] = b1[chB]; s_candi[baseB + 0] = i1[chB];
            s_candv[baseB + 1] = b2[chB]; s_candi[baseB + 1] = i2[chB];
            s_candv[baseB + 2] = b3[chB]; s_candi[baseB + 2] = i3[chB];
        }
    }
    __syncthreads();

    // ---- band-filtered exact fp32 recheck (thread r owns row r) ----
    if (tid < M_TILE) {
        const int r = tid;
        float zr[D_DIM];
#pragma unroll
        for (int d = 0; d < D_DIM; d++) zr[d] = s_z[r * 33 + d];
        float zsq = 0.f;
#pragma unroll
        for (int d = 0; d < D_DIM; d++) zsq = fmaf(zr[d], zr[d], zsq);

        float m = 3.4e38f;
#pragma unroll
        for (int j = 0; j < 24; j++) m = fminf(m, s_candv[r * 24 + j]);
        const float thr = m + 0.05f;

        float bestd = 3.4e38f;
        int   besti = K_CODE;
#pragma unroll 1
        for (int j = 0; j < 24; j++) {
            if (s_candv[r * 24 + j] > thr) continue;
            int k = s_candi[r * 24 + j];
            const float4* wr = reinterpret_cast<const float4*>(
                W + ((size_t)s * K_CODE + k) * D_DIM);
            float dot = 0.f;
#pragma unroll
            for (int jj = 0; jj < 8; jj++) {
                float4 vv = __ldg(&wr[jj]);
                dot = fmaf(zr[jj * 4 + 0], vv.x, dot);
                dot = fmaf(zr[jj * 4 + 1], vv.y, dot);
                dot = fmaf(zr[jj * 4 + 2], vv.z, dot);
                dot = fmaf(zr[jj * 4 + 3], vv.w, dot);
            }
            float d2 = (zsq + s_wsq[k]) - 2.0f * dot;
            if (d2 < bestd || (d2 == bestd && k < besti)) { bestd = d2; besti = k; }
        }

        // gather winner, write output, loss contribution
        const float4* wr = reinterpret_cast<const float4*>(
            W + ((size_t)s * K_CODE + besti) * D_DIM);
        float4* orow = reinterpret_cast<float4*>(
            out + (size_t)(n0 + r) * IN_DIM + s * D_DIM);
        float ls = 0.f;
#pragma unroll
        for (int j = 0; j < 8; j++) {
            float4 vv = __ldg(&wr[j]);
            float a0 = vv.x - zr[j * 4 + 0];
            float a1 = vv.y - zr[j * 4 + 1];
            float a2 = vv.z - zr[j * 4 + 2];
            float a3 = vv.w - zr[j * 4 + 3];
            ls = fmaf(a0, a0, ls); ls = fmaf(a1, a1, ls);
            ls = fmaf(a2, a2, ls); ls = fmaf(a3, a3, ls);
            orow[j] = vv;
        }
        s_loss[r] = ls;
    }
    __syncthreads();

    if (tid == 0) {
        float acc = 0.f;
#pragma unroll
        for (int q = 0; q < M_TILE; q++) acc += s_loss[q];
        g_partial[s * MCTA + blockIdx.x] = acc;
    }

    // ---- fused deterministic finalize: last CTA reduces all partials ----
    __shared__ bool s_last;
    __threadfence();
    if (tid == 0) {
        unsigned int t = atomicAdd(&g_done, 1u);
        s_last = (t == (unsigned int)(NPART - 1));
    }
    __syncthreads();
    if (s_last) {
        float a = 0.f;
        for (int i = tid; i < NPART; i += THREADS) a += g_partial[i];   // fixed order
        float* red = s_z;            // reuse (mainloop done in this CTA)
        red[tid] = a;
        __syncthreads();
#pragma unroll
        for (int off = 64; off > 0; off >>= 1) {
            if (tid < off) red[tid] += red[tid + off];
            __syncthreads();
        }
        if (tid == 0) {
            float mm = red[0] / (float)((size_t)N_TOK * S_CH * D_DIM);
            float loss = (float)S_CH * (mm + 0.001f * mm);
            if (out_size > N_TOK * IN_DIM) out[out_size - 1] = loss;
            g_done = 0;              // reset for next graph replay
        }
    }
}

// ---------------------------------------------------------------------------
extern "C" void kernel_launch(void* const* d_in, const int* in_sizes, int n_in,
                              void* d_out, int out_size) {
    const float* z = (const float*)d_in[0];   // (8192, 1024) f32
    const float* W = (const float*)d_in[1];   // (32, 1024, 32) f32
    float* out = (float*)d_out;

    cudaFuncSetAttribute(vq_main, cudaFuncAttributeMaxDynamicSharedMemorySize, SMEM_TOTAL);

    prep_w<<<(S_CH * K_CODE + 127) / 128, 128>>>(W);

    dim3 grid(MCTA, S_CH);
    vq_main<<<grid, THREADS, SMEM_TOTAL>>>(z, W, out, out_size);
}

// round 6
// speedup vs baseline: 6.2959x; 1.3415x over previous
#include <cuda_runtime.h>
#include <cuda_fp16.h>
#include <cstdint>

#define N_TOK   8192
#define S_CH    32
#define D_DIM   32
#define K_CODE  1024
#define IN_DIM  1024

#define M_TILE  64
#define THREADS 128
#define MCTA    (N_TOK / M_TILE)       // 128
#define NPART   (MCTA * S_CH)          // 4096

#define NCHUNK     8
#define CH_ROWS    128
#define ROW_BYTES  80                  // 32 halfs + 16B pad (ldmatrix bank-safe)
#define CH_BYTES   (CH_ROWS * ROW_BYTES)      // 10240

// ---------------- device scratch ----------------
__device__ float g_wsq[S_CH * K_CODE];
__device__ float g_partial[NPART];
__device__ unsigned int g_done = 0;
__device__ __align__(1024) unsigned char g_Wimg[S_CH * NCHUNK * CH_BYTES]; // 2.6MB

// ---------------- SMEM layout ----------------
#define SM_MBAR   0
#define SM_Z      64       // 64 x 33 f32 = 8448
#define SM_WSQ    8512     // 4096
#define SM_ZH     12608    // 64 x 80B = 5120 (half(-2z) image)
#define SM_CANDV  17728    // 64 x 24 packed f32 = 6144
#define SM_LOSS   23872    // 256
#define SM_B0     24576    // 10240
#define SM_B1     34816    // 10240
#define SMEM_TOTAL 45056

// ---------------- PTX helpers ----------------
__device__ __forceinline__ uint32_t smem_u32(const void* p) {
    uint32_t a;
    asm("{ .reg .u64 t; cvta.to.shared.u64 t, %1; cvt.u32.u64 %0, t; }" : "=r"(a) : "l"(p));
    return a;
}
#define MBAR_INIT(a, c) \
    asm volatile("mbarrier.init.shared.b64 [%0], %1;" :: "r"(a), "r"(c) : "memory")
#define MBAR_EXPECT(a, b) \
    asm volatile("mbarrier.arrive.expect_tx.shared.b64 _, [%0], %1;" :: "r"(a), "r"(b) : "memory")
#define MBAR_WAIT(a, ph) do { \
    uint32_t _m = (a); uint32_t _p = (ph); uint32_t _d; \
    asm volatile("{\n\t.reg .pred p;\n\t" \
        "mbarrier.try_wait.parity.acquire.cta.shared::cta.b64 p, [%1], %2;\n\t" \
        "selp.b32 %0, 1, 0, p;\n\t}" : "=r"(_d) : "r"(_m), "r"(_p) : "memory"); \
    if (!_d) { \
        asm volatile("{\n\t.reg .pred P1;\n\t" \
            "WL_%=:\n\t" \
            "mbarrier.try_wait.parity.acquire.cta.shared::cta.b64 P1, [%0], %1, 0x989680;\n\t" \
            "@P1 bra.uni WD_%=;\n\t" \
            "bra.uni WL_%=;\n\t" \
            "WD_%=:\n\t}" :: "r"(_m), "r"(_p) : "memory"); \
    } } while (0)

__device__ __forceinline__ void bulk_copy(uint32_t dst, const void* src, uint32_t bytes, uint32_t mbar) {
    uint64_t g = (uint64_t)__cvta_generic_to_global(src);
    asm volatile("cp.async.bulk.shared::cta.global.mbarrier::complete_tx::bytes [%0], [%1], %2, [%3];"
        :: "r"(dst), "l"(g), "r"(bytes), "r"(mbar) : "memory");
}
#define LDM_X4(r0, r1, r2, r3, a) \
    asm volatile("ldmatrix.sync.aligned.m8n8.x4.shared.b16 {%0,%1,%2,%3}, [%4];" \
        : "=r"(r0), "=r"(r1), "=r"(r2), "=r"(r3) : "r"(a))
#define MMA16816(c, a, b0, b1) \
    asm volatile("mma.sync.aligned.m16n8k16.row.col.f32.f16.f16.f32 " \
        "{%0,%1,%2,%3}, {%4,%5,%6,%7}, {%8,%9}, {%0,%1,%2,%3};" \
        : "+f"((c)[0]), "+f"((c)[1]), "+f"((c)[2]), "+f"((c)[3]) \
        : "r"((a)[0]), "r"((a)[1]), "r"((a)[2]), "r"((a)[3]), "r"(b0), "r"(b1))
#define MMA16816_INIT(c, a, b0, b1, c0v, c1v) \
    asm volatile("mma.sync.aligned.m16n8k16.row.col.f32.f16.f16.f32 " \
        "{%0,%1,%2,%3}, {%4,%5,%6,%7}, {%8,%9}, {%10,%11,%12,%13};" \
        : "=f"((c)[0]), "=f"((c)[1]), "=f"((c)[2]), "=f"((c)[3]) \
        : "r"((a)[0]), "r"((a)[1]), "r"((a)[2]), "r"((a)[3]), "r"(b0), "r"(b1), \
          "f"(c0v), "f"(c1v), "f"(c0v), "f"(c1v))

// pack k (10 bits) into low mantissa bits: ordering-preserving up to ~1e-4 rel
#define PPACK(v, k) __uint_as_float((__float_as_uint(v) & 0xFFFFFC00u) | (uint32_t)(k))
// packed top-3 insert via min/max sort network (5 FMNMX)
#define PINS3(ch, val) do { \
    float _t = (val); \
    float _n1 = fminf(c1[ch], _t); _t = fmaxf(c1[ch], _t); c1[ch] = _n1; \
    float _n2 = fminf(c2[ch], _t); _t = fmaxf(c2[ch], _t); c2[ch] = _n2; \
    c3[ch] = fminf(c3[ch], _t); } while (0)

// ---------------------------------------------------------------------------
// Kernel 1: prep — wsq + fp16 W image; row staged in regs, 5x ST.128
// ---------------------------------------------------------------------------
__global__ void prep_w(const float* __restrict__ W) {
    int i = blockIdx.x * blockDim.x + threadIdx.x;   // s*1024 + k
    if (i >= S_CH * K_CODE) return;
    int k = i & (K_CODE - 1);
    int s = i >> 10;
    int chunk = k >> 7, row = k & 127;
    const float4* wr = reinterpret_cast<const float4*>(W + (size_t)i * D_DIM);

    float4 stage[5];
    __half2* oh = reinterpret_cast<__half2*>(stage);
    float sq = 0.f;
#pragma unroll
    for (int j = 0; j < 8; j++) {
        float4 v = __ldg(&wr[j]);
        sq = fmaf(v.x, v.x, sq); sq = fmaf(v.y, v.y, sq);
        sq = fmaf(v.z, v.z, sq); sq = fmaf(v.w, v.w, sq);
        oh[j * 2 + 0] = __floats2half2_rn(v.x, v.y);
        oh[j * 2 + 1] = __floats2half2_rn(v.z, v.w);
    }
#pragma unroll
    for (int j = 16; j < 20; j++) oh[j] = __floats2half2_rn(0.f, 0.f);

    float4* dst = reinterpret_cast<float4*>(
        g_Wimg + (size_t)(s * NCHUNK + chunk) * CH_BYTES + (size_t)row * ROW_BYTES);
#pragma unroll
    for (int j = 0; j < 5; j++) dst[j] = stage[j];
    g_wsq[i] = sq;
}

// ---------------------------------------------------------------------------
// Kernel 2: main — 1-pass fp16 screening, packed top-3 chains, band recheck
// ---------------------------------------------------------------------------
__global__ __launch_bounds__(THREADS)
void vq_main(const float* __restrict__ z,
             const float* __restrict__ W,
             float* __restrict__ out,
             int out_size)
{
    extern __shared__ char smem[];
    const uint32_t sb = smem_u32(smem);
    const int tid  = threadIdx.x;
    const int wid  = tid >> 5;
    const int lane = tid & 31;
    const int s    = blockIdx.y;
    const int n0   = blockIdx.x * M_TILE;

    float* s_z     = reinterpret_cast<float*>(smem + SM_Z);     // stride 33
    float* s_wsq   = reinterpret_cast<float*>(smem + SM_WSQ);
    float* s_candv = reinterpret_cast<float*>(smem + SM_CANDV);
    float* s_loss  = reinterpret_cast<float*>(smem + SM_LOSS);

    if (tid == 0) { MBAR_INIT(sb + SM_MBAR, 1); MBAR_INIT(sb + SM_MBAR + 8, 1); }
    __syncthreads();

    if (tid == 0) {
        MBAR_EXPECT(sb + SM_MBAR, CH_BYTES);
        bulk_copy(sb + SM_B0, g_Wimg + (size_t)(s * NCHUNK + 0) * CH_BYTES, CH_BYTES, sb + SM_MBAR);
        MBAR_EXPECT(sb + SM_MBAR + 8, CH_BYTES);
        bulk_copy(sb + SM_B1, g_Wimg + (size_t)(s * NCHUNK + 1) * CH_BYTES, CH_BYTES, sb + SM_MBAR + 8);
    }

    // ---- stage z (fp32) + A image half(-2z) + wsq ----
    {
        const int r = tid >> 1;
        const int h = tid & 1;
        const float4* zr = reinterpret_cast<const float4*>(
            z + (size_t)(n0 + r) * IN_DIM + s * D_DIM) + h * 4;
        __half2* zh = reinterpret_cast<__half2*>(smem + SM_ZH + r * ROW_BYTES + h * 32);
        float*   zf = s_z + r * 33 + h * 16;
#pragma unroll
        for (int j = 0; j < 4; j++) {
            float4 v = zr[j];
            zf[j * 4 + 0] = v.x; zf[j * 4 + 1] = v.y;
            zf[j * 4 + 2] = v.z; zf[j * 4 + 3] = v.w;
            zh[j * 2 + 0] = __floats2half2_rn(-2.f * v.x, -2.f * v.y);
            zh[j * 2 + 1] = __floats2half2_rn(-2.f * v.z, -2.f * v.w);
        }
#pragma unroll
        for (int j = 0; j < K_CODE / THREADS; j++)
            s_wsq[tid + j * THREADS] = g_wsq[s * K_CODE + tid + j * THREADS];
    }
    __syncthreads();

    // ---- A fragments (hi only, 2 k-steps) ----
    uint32_t Ah[2][4];
    {
        const int rowoff = wid * 16 + ((lane >> 3) & 1) * 8 + (lane & 7);
        const int kb = (lane >> 4) & 1;
#pragma unroll
        for (int ks = 0; ks < 2; ks++) {
            uint32_t a = sb + SM_ZH + rowoff * ROW_BYTES + ks * 32 + kb * 16;
            LDM_X4(Ah[ks][0], Ah[ks][1], Ah[ks][2], Ah[ks][3], a);
        }
    }

    const int g   = lane >> 2;
    const int tig = lane & 3;

    // 4 chains/thread (rowA/t0, rowA/t1, rowB/t0, rowB/t1), packed top-3
    float c1[4], c2[4], c3[4];
#pragma unroll
    for (int c = 0; c < 4; c++) { c1[c] = 3.4e38f; c2[c] = 3.4e38f; c3[c] = 3.4e38f; }

    const int bnrow = ((lane & 16) ? 8 : 0) + (lane & 7);
    const int bkb   = (lane >> 3) & 1;

#pragma unroll 1
    for (int c = 0; c < NCHUNK; c++) {
        MBAR_WAIT(sb + SM_MBAR + (c & 1) * 8, (c >> 1) & 1);
        const uint32_t whb = sb + ((c & 1) ? SM_B1 : SM_B0);

#pragma unroll 2
        for (int g2 = 0; g2 < 8; g2++) {
            const uint32_t boff = (uint32_t)(g2 * 16 + bnrow) * ROW_BYTES + bkb * 16;
            uint32_t bh0[4], bh1[4];
            LDM_X4(bh0[0], bh0[1], bh0[2], bh0[3], whb + boff);        // ks0
            LDM_X4(bh1[0], bh1[1], bh1[2], bh1[3], whb + boff + 32);   // ks1

            const int kbase = c * 128 + g2 * 16;
            const int col0 = kbase + tig * 2;
            const int col2 = kbase + 8 + tig * 2;
            float2 w01 = *reinterpret_cast<const float2*>(&s_wsq[col0]);
            float2 w23 = *reinterpret_cast<const float2*>(&s_wsq[col2]);

            float acc0[4], acc1[4];
            MMA16816_INIT(acc0, Ah[0], bh0[0], bh0[1], w01.x, w01.y);
            MMA16816     (acc0, Ah[1], bh1[0], bh1[1]);
            MMA16816_INIT(acc1, Ah[0], bh0[2], bh0[3], w23.x, w23.y);
            MMA16816     (acc1, Ah[1], bh1[2], bh1[3]);

            PINS3(0, PPACK(acc0[0], col0));
            PINS3(0, PPACK(acc0[1], col0 + 1));
            PINS3(1, PPACK(acc1[0], col2));
            PINS3(1, PPACK(acc1[1], col2 + 1));
            PINS3(2, PPACK(acc0[2], col0));
            PINS3(2, PPACK(acc0[3], col0 + 1));
            PINS3(3, PPACK(acc1[2], col2));
            PINS3(3, PPACK(acc1[3], col2 + 1));
        }
        __syncthreads();
        if (tid == 0 && c + 2 < NCHUNK) {
            MBAR_EXPECT(sb + SM_MBAR + (c & 1) * 8, CH_BYTES);
            bulk_copy(sb + ((c & 1) ? SM_B1 : SM_B0),
                      g_Wimg + (size_t)(s * NCHUNK + c + 2) * CH_BYTES, CH_BYTES,
                      sb + SM_MBAR + (c & 1) * 8);
        }
    }

    // ---- dump candidates: 24 packed per row ----
    {
        const int rowA = wid * 16 + g;
        const int rowB = rowA + 8;
#pragma unroll
        for (int t = 0; t < 2; t++) {
            int baseA = rowA * 24 + t * 12 + tig * 3;
            int baseB = rowB * 24 + t * 12 + tig * 3;
            s_candv[baseA + 0] = c1[t];     s_candv[baseA + 1] = c2[t];
            s_candv[baseA + 2] = c3[t];
            s_candv[baseB + 0] = c1[2 + t]; s_candv[baseB + 1] = c2[2 + t];
            s_candv[baseB + 2] = c3[2 + t];
        }
    }
    __syncthreads();

    // ---- band-filtered exact fp32 recheck (thread r owns row r) ----
    if (tid < M_TILE) {
        const int r = tid;
        float zr[D_DIM];
#pragma unroll
        for (int d = 0; d < D_DIM; d++) zr[d] = s_z[r * 33 + d];
        float zsq = 0.f;
#pragma unroll
        for (int d = 0; d < D_DIM; d++) zsq = fmaf(zr[d], zr[d], zsq);

        float m = 3.4e38f;
#pragma unroll
        for (int j = 0; j < 24; j++) m = fminf(m, s_candv[r * 24 + j]);
        const float thr = m + 0.06f;

        float bestd = 3.4e38f;
        int   besti = K_CODE;
#pragma unroll 1
        for (int j = 0; j < 24; j++) {
            float pv = s_candv[r * 24 + j];
            if (pv > thr) continue;
            int k = (int)(__float_as_uint(pv) & 0x3FFu);
            const float4* wr = reinterpret_cast<const float4*>(
                W + ((size_t)s * K_CODE + k) * D_DIM);
            float dot = 0.f;
#pragma unroll
            for (int jj = 0; jj < 8; jj++) {
                float4 vv = __ldg(&wr[jj]);
                dot = fmaf(zr[jj * 4 + 0], vv.x, dot);
                dot = fmaf(zr[jj * 4 + 1], vv.y, dot);
                dot = fmaf(zr[jj * 4 + 2], vv.z, dot);
                dot = fmaf(zr[jj * 4 + 3], vv.w, dot);
            }
            float d2 = (zsq + s_wsq[k]) - 2.0f * dot;
            if (d2 < bestd || (d2 == bestd && k < besti)) { bestd = d2; besti = k; }
        }

        const float4* wr = reinterpret_cast<const float4*>(
            W + ((size_t)s * K_CODE + besti) * D_DIM);
        float4* orow = reinterpret_cast<float4*>(
            out + (size_t)(n0 + r) * IN_DIM + s * D_DIM);
        float ls = 0.f;
#pragma unroll
        for (int j = 0; j < 8; j++) {
            float4 vv = __ldg(&wr[j]);
            float a0 = vv.x - zr[j * 4 + 0];
            float a1 = vv.y - zr[j * 4 + 1];
            float a2 = vv.z - zr[j * 4 + 2];
            float a3 = vv.w - zr[j * 4 + 3];
            ls = fmaf(a0, a0, ls); ls = fmaf(a1, a1, ls);
            ls = fmaf(a2, a2, ls); ls = fmaf(a3, a3, ls);
            orow[j] = vv;
        }
        s_loss[r] = ls;
    }
    __syncthreads();

    if (tid == 0) {
        float acc = 0.f;
#pragma unroll
        for (int q = 0; q < M_TILE; q++) acc += s_loss[q];
        g_partial[s * MCTA + blockIdx.x] = acc;
    }

    // ---- fused deterministic finalize: last CTA reduces all partials ----
    __shared__ bool s_last;
    __threadfence();
    if (tid == 0) {
        unsigned int t = atomicAdd(&g_done, 1u);
        s_last = (t == (unsigned int)(NPART - 1));
    }
    __syncthreads();
    if (s_last) {
        float a = 0.f;
        for (int i = tid; i < NPART; i += THREADS) a += g_partial[i];   // fixed order
        float* red = s_z;
        red[tid] = a;
        __syncthreads();
#pragma unroll
        for (int off = 64; off > 0; off >>= 1) {
            if (tid < off) red[tid] += red[tid + off];
            __syncthreads();
        }
        if (tid == 0) {
            float mm = red[0] / (float)((size_t)N_TOK * S_CH * D_DIM);
            float loss = (float)S_CH * (mm + 0.001f * mm);
            if (out_size > N_TOK * IN_DIM) out[out_size - 1] = loss;
            g_done = 0;
        }
    }
}

// ---------------------------------------------------------------------------
extern "C" void kernel_launch(void* const* d_in, const int* in_sizes, int n_in,
                              void* d_out, int out_size) {
    const float* z = (const float*)d_in[0];   // (8192, 1024) f32
    const float* W = (const float*)d_in[1];   // (32, 1024, 32) f32
    float* out = (float*)d_out;

    cudaFuncSetAttribute(vq_main, cudaFuncAttributeMaxDynamicSharedMemorySize, SMEM_TOTAL);

    prep_w<<<(S_CH * K_CODE + 255) / 256, 256>>>(W);

    dim3 grid(MCTA, S_CH);
    vq_main<<<grid, THREADS, SMEM_TOTAL>>>(z, W, out, out_size);
}